// round 1
// baseline (speedup 1.0000x reference)
#include <cuda_runtime.h>
#include <cuda_bf16.h>

// SelfAttention_34230889349396 — algebraic collapse.
//
// scores = (q @ k.T) * 1/(1024**5)  ->  |scores| <= ~2e-13.
// fp32 exp(s - max) == 1.0f exactly for such s, so softmax weights are exactly
// 1/8192 and the output is row-broadcast of  (mean_rows(x)) @ Wv.
// Only x and Wv matter. Total traffic ~68 MB -> HBM-bound, ~15 us.

#define D      1024
#define NROWS  8192
#define D4     (D / 4)          // 256 float4 columns

// Scratch (no device allocation allowed; __device__ globals per pitfalls.md)
__device__ float g_xsum[D];     // column sums of x
__device__ float g_ovec[D];     // (mean_rows(x)) @ Wv

// ---------------------------------------------------------------------------
// 1) zero the scratch (graph-replayed every launch -> must re-zero each call)
__global__ void k_zero() {
    int t = threadIdx.x;        // 1024 threads
    g_xsum[t] = 0.0f;
    g_ovec[t] = 0.0f;
}

// ---------------------------------------------------------------------------
// 2) column sums of x [NROWS, D].
//    grid.x = 256 row-chunks of 32 rows; block = 256 threads, thread t owns
//    float4 column t. Loads fully coalesced; 256 atomics per address total.
#define CS_BLOCKS 256
#define CS_ROWS   (NROWS / CS_BLOCKS)   // 32
__global__ void k_colsum(const float* __restrict__ x) {
    const float4* __restrict__ x4 = reinterpret_cast<const float4*>(x);
    const int t    = threadIdx.x;                 // 0..255 (float4 column)
    const int row0 = blockIdx.x * CS_ROWS;
    float4 acc = make_float4(0.f, 0.f, 0.f, 0.f);
#pragma unroll 8
    for (int i = 0; i < CS_ROWS; ++i) {
        float4 v = x4[(size_t)(row0 + i) * D4 + t];
        acc.x += v.x; acc.y += v.y; acc.z += v.z; acc.w += v.w;
    }
    atomicAdd(&g_xsum[t * 4 + 0], acc.x);
    atomicAdd(&g_xsum[t * 4 + 1], acc.y);
    atomicAdd(&g_xsum[t * 4 + 2], acc.z);
    atomicAdd(&g_xsum[t * 4 + 3], acc.w);
}

// ---------------------------------------------------------------------------
// 3) ovec[c] = (1/NROWS) * sum_k xsum[k] * Wv[k*D + c]
//    grid.x = 16 k-chunks of 64; block = 1024 threads (one per output col).
#define MV_CHUNKS 16
#define MV_K      (D / MV_CHUNKS)       // 64
__global__ void k_matvec(const float* __restrict__ Wv) {
    const int c  = threadIdx.x;         // 0..1023
    const int k0 = blockIdx.x * MV_K;
    float acc = 0.f;
#pragma unroll 8
    for (int kk = 0; kk < MV_K; ++kk) {
        const int k = k0 + kk;
        acc = fmaf(g_xsum[k], __ldg(&Wv[(size_t)k * D + c]), acc);
    }
    atomicAdd(&g_ovec[c], acc * (1.0f / (float)NROWS));
}

// ---------------------------------------------------------------------------
// 4) broadcast ovec to every output row. grid.x = 1024 blocks x 8 rows,
//    block = 256 threads, float4 stores (32 MB write, HBM-bound).
#define BC_ROWS 8
__global__ void k_bcast(float* __restrict__ out) {
    const int t = threadIdx.x;          // float4 column
    const float4 v = reinterpret_cast<const float4*>(g_ovec)[t];
    float4* __restrict__ out4 = reinterpret_cast<float4*>(out);
    const size_t row0 = (size_t)blockIdx.x * BC_ROWS;
#pragma unroll
    for (int i = 0; i < BC_ROWS; ++i)
        out4[(row0 + i) * D4 + t] = v;
}

// ---------------------------------------------------------------------------
extern "C" void kernel_launch(void* const* d_in, const int* in_sizes, int n_in,
                              void* d_out, int out_size) {
    const float* x  = (const float*)d_in[0];   // [8192, 1024]
    // d_in[1] = Wq, d_in[2] = Wk — provably unused (softmax is exactly uniform)
    const float* Wv = (const float*)d_in[3];   // [1024, 1024]
    float* out = (float*)d_out;                // [8192, 1024]

    k_zero<<<1, D>>>();
    k_colsum<<<CS_BLOCKS, 256>>>(x);
    k_matvec<<<MV_CHUNKS, D>>>(Wv);
    k_bcast<<<NROWS / BC_ROWS, 256>>>(out);
}

// round 2
// speedup vs baseline: 1.5832x; 1.5832x over previous
#include <cuda_runtime.h>
#include <cuda_bf16.h>

// SelfAttention_34230889349396 — algebraic collapse (see R1):
// scores * 1/(1024**5) ~ 2e-13  ->  fp32 softmax is EXACTLY uniform (1/8192)
// => out[i,:] = mean_rows(x) @ Wv, broadcast to all rows. Only x and Wv matter.
//
// R2: remove atomic serialization in colsum (partials + smem reduce in matvec),
// fold scratch zeroing into colsum block 0, widen bcast grid.

#define D      1024
#define NROWS  8192
#define D4     (D / 4)            // 256 float4 columns

#define CS_BLOCKS 256
#define CS_ROWS   (NROWS / CS_BLOCKS)   // 32

#define MV_BLOCKS 16
#define MV_K      (D / MV_BLOCKS)       // 64

// Scratch (__device__ globals — no allocation allowed)
__device__ float4 g_part4[CS_BLOCKS * D4];  // per-block column partial sums [256][1024]f
__device__ float  g_ovec[D];                // mean_rows(x) @ Wv

// ---------------------------------------------------------------------------
// 1) column partial sums of x [NROWS, D]; no atomics.
//    Block b sums rows [32b, 32b+32); thread t owns float4 column t.
//    Block 0 also zeroes g_ovec (ordered before k_matvec by the stream).
__global__ void k_colsum(const float* __restrict__ x) {
    const float4* __restrict__ x4 = reinterpret_cast<const float4*>(x);
    const int t = threadIdx.x;              // 0..255
    const int b = blockIdx.x;

    if (b == 0)
        reinterpret_cast<float4*>(g_ovec)[t] = make_float4(0.f, 0.f, 0.f, 0.f);

    const int row0 = b * CS_ROWS;
    float4 acc = make_float4(0.f, 0.f, 0.f, 0.f);
#pragma unroll 8
    for (int i = 0; i < CS_ROWS; ++i) {
        float4 v = x4[(size_t)(row0 + i) * D4 + t];
        acc.x += v.x; acc.y += v.y; acc.z += v.z; acc.w += v.w;
    }
    g_part4[b * D4 + t] = acc;
}

// ---------------------------------------------------------------------------
// 2) reduce partials for a 64-wide k-slice, then ovec[c] += sum_k xsum[k]*Wv[k,c].
//    16 blocks x 1024 threads. Atomics: only 16 per g_ovec address (negligible).
__global__ void k_matvec(const float* __restrict__ Wv) {
    __shared__ float red[16][MV_K];     // [partial-group][k]
    __shared__ float xs[MV_K];

    const int t  = threadIdx.x;         // 0..1023
    const int k0 = blockIdx.x * MV_K;
    const int kk = t & (MV_K - 1);      // 0..63
    const int p  = t >> 6;              // 0..15

    // Reduce 256 block-partials for columns [k0, k0+64): 16 threads/column.
    const float* __restrict__ part = reinterpret_cast<const float*>(g_part4);
    float s = 0.f;
#pragma unroll
    for (int i = 0; i < 16; ++i)
        s += part[(size_t)(p * 16 + i) * D + k0 + kk];
    red[p][kk] = s;
    __syncthreads();

    if (t < MV_K) {
        float tot = 0.f;
#pragma unroll
        for (int q = 0; q < 16; ++q) tot += red[q][t];
        xs[t] = tot * (1.0f / (float)NROWS);   // fold the 1/N softmax weight here
    }
    __syncthreads();

    // Mat-vec slice: thread t = output column c.
    float acc = 0.f;
#pragma unroll 16
    for (int k = 0; k < MV_K; ++k)
        acc = fmaf(xs[k], __ldg(&Wv[(size_t)(k0 + k) * D + t]), acc);
    atomicAdd(&g_ovec[t], acc);
}

// ---------------------------------------------------------------------------
// 3) broadcast ovec to all 8192 output rows. 2048 blocks x 1024 threads,
//    one float4 store per thread (4 rows per block).
__global__ void k_bcast(float* __restrict__ out) {
    const int t   = threadIdx.x;
    const int col = t & (D4 - 1);               // 0..255
    const int r   = t >> 8;                     // 0..3
    const float4 v = reinterpret_cast<const float4*>(g_ovec)[col];
    const size_t row = (size_t)blockIdx.x * 4 + r;
    reinterpret_cast<float4*>(out)[row * D4 + col] = v;
}

// ---------------------------------------------------------------------------
extern "C" void kernel_launch(void* const* d_in, const int* in_sizes, int n_in,
                              void* d_out, int out_size) {
    const float* x  = (const float*)d_in[0];   // [8192, 1024]
    // d_in[1]=Wq, d_in[2]=Wk provably unused (softmax exactly uniform)
    const float* Wv = (const float*)d_in[3];   // [1024, 1024]
    float* out = (float*)d_out;                // [8192, 1024]

    k_colsum<<<CS_BLOCKS, 256>>>(x);
    k_matvec<<<MV_BLOCKS, 1024>>>(Wv);
    k_bcast<<<NROWS / 4, 1024>>>(out);
}